// round 10
// baseline (speedup 1.0000x reference)
#include <cuda_runtime.h>
#include <math.h>

#define Bsz  128
#define Tlen 1024
#define Hd   256
#define NOUT 2

typedef unsigned long long u64;

// Scratch buffers (device globals — allocation is forbidden)
__device__ float g_bufA[Bsz * Tlen * Hd];  // pre-activations
__device__ float g_bufB[Bsz * Tlen * Hd];  // layer-1 hidden states

// ---------- packed fp32x2 helpers (full-rate fp32 path on sm_103a) ----------
__device__ __forceinline__ void fma2(u64& acc, u64 a, u64 b) {
    asm("fma.rn.f32x2 %0, %1, %2, %0;" : "+l"(acc) : "l"(a), "l"(b));
}
__device__ __forceinline__ u64 add2(u64 a, u64 b) {
    u64 r; asm("add.rn.f32x2 %0, %1, %2;" : "=l"(r) : "l"(a), "l"(b)); return r;
}
__device__ __forceinline__ u64 dup2(float x) {
    u64 r; asm("mov.b64 %0, {%1, %1};" : "=l"(r) : "f"(x)); return r;
}
__device__ __forceinline__ float2 unpk(u64 v) {
    float2 r; asm("mov.b64 {%0, %1}, %2;" : "=f"(r.x), "=f"(r.y) : "l"(v)); return r;
}

// =============================================================================
// GEMM (R5 version — measured-in-context ~597us): out = A @ W^T + bias
// M=131072, N=K=256. Tile 128x128, 256 threads, K staged in 4 chunks of 64,
// next A chunk prefetched into registers before the compute barrier.
// =============================================================================
#define WS_STRIDE 130
#define AS_STRIDE 129
#define GEMM_SMEM ((Hd * WS_STRIDE + 64 * AS_STRIDE) * 4)

__global__ void __launch_bounds__(256, 1) gemm_kernel(
    const float* __restrict__ A, const float* __restrict__ W,
    const float* __restrict__ bias, float* __restrict__ out)
{
    extern __shared__ float sm[];
    float* Ws = sm;                    // [K=256][130]
    float* As = sm + Hd * WS_STRIDE;   // [64][129]

    const int t   = threadIdx.x;
    const int nt  = blockIdx.x & 1;
    const int mt  = blockIdx.x >> 1;
    const int m0  = mt * 128, n0 = nt * 128;
    const int kq  = t & 15;
    const int rn  = t >> 4;
    const int ml  = t & 15;
    const int tn2 = (t >> 4) << 1;

    const float4* W4 = (const float4*)(W + (size_t)n0 * Hd);
    #pragma unroll
    for (int p = 0; p < 8; ++p) {
        int row = rn + (p << 4);
        #pragma unroll
        for (int q = 0; q < 4; ++q) {
            float4 v = W4[row * 64 + (q << 4) + kq];
            int k = (((q << 4) + kq) << 2);
            Ws[(k + 0) * WS_STRIDE + row] = v.x;
            Ws[(k + 1) * WS_STRIDE + row] = v.y;
            Ws[(k + 2) * WS_STRIDE + row] = v.z;
            Ws[(k + 3) * WS_STRIDE + row] = v.w;
        }
    }

    u64 acc[8][4];
    #pragma unroll
    for (int i = 0; i < 8; ++i)
        #pragma unroll
        for (int j = 0; j < 4; ++j) acc[i][j] = 0ull;

    const float4* A4 = (const float4*)(A + (size_t)m0 * Hd);

    float4 v[8];
    #pragma unroll
    for (int p = 0; p < 8; ++p)
        v[p] = A4[(rn + (p << 4)) * 64 + kq];

    for (int s = 0; s < 4; ++s) {
        __syncthreads();
        #pragma unroll
        for (int p = 0; p < 8; ++p) {
            int row = rn + (p << 4);
            int k = kq << 2;
            As[(k + 0) * AS_STRIDE + row] = v[p].x;
            As[(k + 1) * AS_STRIDE + row] = v[p].y;
            As[(k + 2) * AS_STRIDE + row] = v[p].z;
            As[(k + 3) * AS_STRIDE + row] = v[p].w;
        }
        if (s < 3) {
            #pragma unroll
            for (int p = 0; p < 8; ++p)
                v[p] = A4[(rn + (p << 4)) * 64 + ((s + 1) << 4) + kq];
        }
        __syncthreads();

        const int kbase = s << 6;
        #pragma unroll 4
        for (int kk = 0; kk < 64; ++kk) {
            u64 ad[8];
            #pragma unroll
            for (int i = 0; i < 8; ++i)
                ad[i] = dup2(As[kk * AS_STRIDE + ml + (i << 4)]);
            u64 bp[4];
            #pragma unroll
            for (int j = 0; j < 4; ++j)
                bp[j] = *(const u64*)&Ws[(kbase + kk) * WS_STRIDE + tn2 + (j << 5)];
            #pragma unroll
            for (int i = 0; i < 8; ++i)
                #pragma unroll
                for (int j = 0; j < 4; ++j)
                    fma2(acc[i][j], ad[i], bp[j]);
        }
    }

    #pragma unroll
    for (int j = 0; j < 4; ++j) {
        int n = n0 + tn2 + (j << 5);
        float bv0 = bias[n], bv1 = bias[n + 1];
        #pragma unroll
        for (int i = 0; i < 8; ++i) {
            int m = m0 + ml + (i << 4);
            float2 vv = unpk(acc[i][j]);
            float2 r; r.x = vv.x + bv0; r.y = vv.y + bv1;
            *(float2*)&out[(size_t)m * Hd + n] = r;
        }
    }
}

// =============================================================================
// Recurrence v7: 1 CTA = 1 batch row, 256 threads, 1 thread per output.
// Thread j computes the FULL dot over all 256 h values -> no reduction,
// no shuffle, one barrier per step. Every h LDS.128 is a warp-wide broadcast
// (all lanes same address) -> 1 wavefront each.
// Weights: 256 floats/thread = 160 in registers (reg cap 255 at 256 thr)
//          + 96 in smem.
// =============================================================================
#define RREG 40   // ulonglong2 in registers (160 floats)
#define RSM  24   // ulonglong2 in smem (96 floats)
#define REC_SMEM (2 * 256 * 4 + RSM * 256 * 16)

__device__ __forceinline__ float fast_tanh(float x) {
    float e = __expf(2.0f * x);
    return 1.0f - 2.0f * __fdividef(1.0f, e + 1.0f);
}

template<bool WRITE_H, bool FINAL>
__global__ void __launch_bounds__(256, 1) recur_kernel(
    const float* __restrict__ pre, const float* __restrict__ Whh,
    float* __restrict__ hout,
    const float* __restrict__ fcw, const float* __restrict__ fcb,
    float* __restrict__ out)
{
    extern __shared__ float smf[];
    float* hbuf = smf;                              // [2][256] ping-pong h
    ulonglong2* Wsm = (ulonglong2*)(smf + 512);     // [RSM][256]

    const int t = threadIdx.x;   // output index j
    const int b = blockIdx.x;

    // This thread's full weight row: 40 f4 -> regs, 24 f4 -> smem
    const ulonglong2* wg = (const ulonglong2*)(Whh + (size_t)t * Hd);
    ulonglong2 wr[RREG];
    #pragma unroll
    for (int c = 0; c < RREG; ++c) wr[c] = wg[c];
    #pragma unroll
    for (int c = 0; c < RSM; ++c) Wsm[c * 256 + t] = wg[RREG + c];

    hbuf[t] = 0.f;
    hbuf[256 + t] = 0.f;

    const float* preb = pre + (size_t)b * Tlen * Hd;
    float p = preb[t];
    __syncthreads();

    for (int step = 0; step < Tlen; ++step) {
        int sn = (step + 1 < Tlen) ? step + 1 : step;
        float pn = preb[sn * Hd + t];   // prefetch next pre

        const ulonglong2* hb = (const ulonglong2*)(hbuf + (step & 1) * 256);

        u64 a0 = 0ull, a1 = 0ull, a2 = 0ull, a3 = 0ull;
        u64 a4 = 0ull, a5 = 0ull, a6 = 0ull, a7 = 0ull;

        // smem-resident weights first (chunks RREG..63): fill LSU early
        #pragma unroll
        for (int c = 0; c < RSM; c += 2) {
            ulonglong2 hv = hb[RREG + c];
            ulonglong2 wv = Wsm[c * 256 + t];
            fma2(a4, wv.x, hv.x);
            fma2(a5, wv.y, hv.y);
            ulonglong2 hw = hb[RREG + c + 1];
            ulonglong2 ww = Wsm[(c + 1) * 256 + t];
            fma2(a6, ww.x, hw.x);
            fma2(a7, ww.y, hw.y);
        }
        // register-resident weights (chunks 0..RREG-1)
        #pragma unroll
        for (int c = 0; c < RREG; c += 2) {
            ulonglong2 hv = hb[c];
            fma2(a0, wr[c].x, hv.x);
            fma2(a1, wr[c].y, hv.y);
            ulonglong2 hw = hb[c + 1];
            fma2(a2, wr[c + 1].x, hw.x);
            fma2(a3, wr[c + 1].y, hw.y);
        }

        u64 s01 = add2(add2(add2(a0, a1), add2(a2, a3)),
                       add2(add2(a4, a5), add2(a6, a7)));
        float2 f = unpk(s01);
        float hn = fast_tanh(p + f.x + f.y);

        hbuf[((step + 1) & 1) * 256 + t] = hn;
        if (WRITE_H)
            hout[((size_t)b * Tlen + step) * Hd + t] = hn;
        __syncthreads();
        p = pn;
    }

    if (FINAL) {
        // final h in parity (Tlen & 1) == 0
        if (t < 64) {
            int o = t >> 5, lane = t & 31;
            float s = 0.f;
            #pragma unroll
            for (int q = 0; q < 8; ++q) {
                int jj = lane + (q << 5);
                s += hbuf[jj] * fcw[o * Hd + jj];
            }
            #pragma unroll
            for (int off = 16; off; off >>= 1)
                s += __shfl_down_sync(0xffffffffu, s, off);
            if (lane == 0) out[b * NOUT + o] = s + fcb[o];
        }
    }
}

extern "C" void kernel_launch(void* const* d_in, const int* in_sizes, int n_in,
                              void* d_out, int out_size) {
    const float* x    = (const float*)d_in[0];
    const float* Wxh0 = (const float*)d_in[1];
    const float* Whh0 = (const float*)d_in[2];
    const float* b0   = (const float*)d_in[3];
    const float* Wxh1 = (const float*)d_in[4];
    const float* Whh1 = (const float*)d_in[5];
    const float* b1   = (const float*)d_in[6];
    const float* fcw  = (const float*)d_in[7];
    const float* fcb  = (const float*)d_in[8];
    float* out = (float*)d_out;

    float *bufA = nullptr, *bufB = nullptr;
    cudaGetSymbolAddress((void**)&bufA, g_bufA);
    cudaGetSymbolAddress((void**)&bufB, g_bufB);

    cudaFuncSetAttribute(gemm_kernel,
        cudaFuncAttributeMaxDynamicSharedMemorySize, GEMM_SMEM);
    cudaFuncSetAttribute(recur_kernel<true, false>,
        cudaFuncAttributeMaxDynamicSharedMemorySize, REC_SMEM);
    cudaFuncSetAttribute(recur_kernel<false, true>,
        cudaFuncAttributeMaxDynamicSharedMemorySize, REC_SMEM);

    // Layer 1
    gemm_kernel<<<2048, 256, GEMM_SMEM>>>(x, Wxh0, b0, bufA);
    recur_kernel<true, false><<<Bsz, 256, REC_SMEM>>>(
        bufA, Whh0, bufB, nullptr, nullptr, nullptr);

    // Layer 2 + head
    gemm_kernel<<<2048, 256, GEMM_SMEM>>>(bufB, Wxh1, b1, bufA);
    recur_kernel<false, true><<<Bsz, 256, REC_SMEM>>>(
        bufA, Whh1, nullptr, fcw, fcb, out);
}

// round 12
// speedup vs baseline: 1.2982x; 1.2982x over previous
#include <cuda_runtime.h>
#include <cuda_bf16.h>
#include <math.h>
#include <cstdint>

#define Bsz  128
#define Tlen 1024
#define Hd   256
#define NOUT 2

typedef unsigned long long u64;

// Scratch buffers (device globals — allocation is forbidden)
__device__ float g_bufA[Bsz * Tlen * Hd];  // pre-activations
__device__ float g_bufB[Bsz * Tlen * Hd];  // layer-1 hidden states

// ---------- packed fp32x2 helpers ----------
__device__ __forceinline__ void fma2(u64& acc, u64 a, u64 b) {
    asm("fma.rn.f32x2 %0, %1, %2, %0;" : "+l"(acc) : "l"(a), "l"(b));
}
__device__ __forceinline__ u64 add2(u64 a, u64 b) {
    u64 r; asm("add.rn.f32x2 %0, %1, %2;" : "=l"(r) : "l"(a), "l"(b)); return r;
}
__device__ __forceinline__ float2 unpk(u64 v) {
    float2 r; asm("mov.b64 {%0, %1}, %2;" : "=f"(r.x), "=f"(r.y) : "l"(v)); return r;
}

__device__ __forceinline__ uint32_t smem_to_u32(const void* p) {
    uint32_t a;
    asm("{ .reg .u64 t; cvta.to.shared.u64 t, %1; cvt.u32.u64 %0, t; }"
        : "=r"(a) : "l"(p));
    return a;
}

// ---------- HMMA helpers (sm_80-era, valid on plain sm_103 target) ----------
#define LDSM_X4(r0, r1, r2, r3, addr)                                         \
    asm volatile("ldmatrix.sync.aligned.m8n8.x4.shared.b16 {%0,%1,%2,%3}, [%4];" \
                 : "=r"(r0), "=r"(r1), "=r"(r2), "=r"(r3) : "r"(addr))

#define MMA16816(d, a, b0, b1)                                                \
    asm volatile("mma.sync.aligned.m16n8k16.row.col.f32.bf16.bf16.f32 "       \
                 "{%0,%1,%2,%3}, {%4,%5,%6,%7}, {%8,%9}, {%0,%1,%2,%3};"      \
                 : "+f"((d)[0]), "+f"((d)[1]), "+f"((d)[2]), "+f"((d)[3])     \
                 : "r"((a)[0]), "r"((a)[1]), "r"((a)[2]), "r"((a)[3]),        \
                   "r"(b0), "r"(b1))

// =============================================================================
// HMMA GEMM: out[m][n] = sum_k A[m][k]*W[n][k] + bias[n]
// M=131072, N=256, K=256. CTA tile 128m x 128n; 8 warps of 32m x 64n.
// bf16 hi/lo split (3 passes: hi*hi, hi*lo, lo*hi), fp32 accumulators.
// K staged in 4 chunks of 64 into 4 smem buffers, stride 72 bf16 (144B):
// ldmatrix rows spaced 36 words == 4 mod 32 -> conflict-free.
// 2 CTAs/SM so one CTA's staging overlaps the other's MMA.
// =============================================================================
#define GH_STRIDE 144                  // bytes per 64-k row (72 bf16)
#define GH_TILE   (128 * GH_STRIDE)    // 18432 B per buffer
#define GH_SMEM   (4 * GH_TILE)        // 73728 B

__device__ __forceinline__ void cv_store(char* hi, char* lo, uint32_t off, float4 v) {
    __nv_bfloat162 h01 = __floats2bfloat162_rn(v.x, v.y);
    __nv_bfloat162 h23 = __floats2bfloat162_rn(v.z, v.w);
    float2 f01 = __bfloat1622float2(h01);
    float2 f23 = __bfloat1622float2(h23);
    __nv_bfloat162 l01 = __floats2bfloat162_rn(v.x - f01.x, v.y - f01.y);
    __nv_bfloat162 l23 = __floats2bfloat162_rn(v.z - f23.x, v.w - f23.y);
    uint32_t uh01, uh23, ul01, ul23;
    memcpy(&uh01, &h01, 4); memcpy(&uh23, &h23, 4);
    memcpy(&ul01, &l01, 4); memcpy(&ul23, &l23, 4);
    *(uint2*)(hi + off) = make_uint2(uh01, uh23);
    *(uint2*)(lo + off) = make_uint2(ul01, ul23);
}

__global__ void __launch_bounds__(256, 2) gemm_hmma_kernel(
    const float* __restrict__ A, const float* __restrict__ W,
    const float* __restrict__ bias, float* __restrict__ out)
{
    extern __shared__ char smem[];
    char* pAhi = smem;
    char* pAlo = smem + GH_TILE;
    char* pBhi = smem + 2 * GH_TILE;
    char* pBlo = smem + 3 * GH_TILE;
    const uint32_t sAhi = smem_to_u32(pAhi);
    const uint32_t sAlo = sAhi + GH_TILE;
    const uint32_t sBhi = sAhi + 2 * GH_TILE;
    const uint32_t sBlo = sAhi + 3 * GH_TILE;

    const int t    = threadIdx.x;
    const int lane = t & 31;
    const int wid  = t >> 5;
    const int nt   = blockIdx.x & 1;
    const int mt   = blockIdx.x >> 1;
    const int m0   = mt * 128, n0 = nt * 128;
    const int wm   = (wid & 3) * 32;    // warp m offset in tile
    const int wn   = (wid >> 2) * 64;   // warp n offset in tile

    float acc[2][8][4];
    #pragma unroll
    for (int f = 0; f < 2; ++f)
        #pragma unroll
        for (int n8 = 0; n8 < 8; ++n8)
            #pragma unroll
            for (int e = 0; e < 4; ++e) acc[f][n8][e] = 0.f;

    const float* Ab = A + (size_t)m0 * Hd;
    const float* Wb = W + (size_t)n0 * Hd;

    // lane-dependent ldmatrix address components
    const uint32_t aRowOff = (uint32_t)(lane & 15) * GH_STRIDE +
                             (uint32_t)(lane >> 4) * 16;            // k-half *8*2B
    const uint32_t bRowOff = ((uint32_t)((lane >> 4) << 3) + (lane & 7)) * GH_STRIDE +
                             (uint32_t)((lane >> 3) & 1) * 16;

    for (int chunk = 0; chunk < 4; ++chunk) {
        __syncthreads();   // previous chunk's compute done reading smem
        const int kb = chunk << 6;
        #pragma unroll
        for (int i = 0; i < 8; ++i) {
            int idx = t + (i << 8);
            int row = idx >> 4, q = idx & 15;
            uint32_t off = (uint32_t)row * GH_STRIDE + (uint32_t)q * 8;
            float4 va = *(const float4*)&Ab[row * Hd + kb + (q << 2)];
            cv_store(pAhi, pAlo, off, va);
            float4 vb = *(const float4*)&Wb[row * Hd + kb + (q << 2)];
            cv_store(pBhi, pBlo, off, vb);
        }
        __syncthreads();

        #pragma unroll
        for (int pass = 0; pass < 3; ++pass) {
            const uint32_t ab = (pass == 2) ? sAlo : sAhi;
            const uint32_t bb = (pass == 1) ? sBlo : sBhi;
            const uint32_t aaddr = ab + (uint32_t)wm * GH_STRIDE + aRowOff;
            const uint32_t baddr = bb + (uint32_t)wn * GH_STRIDE + bRowOff;
            #pragma unroll
            for (int ks = 0; ks < 4; ++ks) {
                uint32_t a0[4], a1[4];
                LDSM_X4(a0[0], a0[1], a0[2], a0[3], aaddr + ks * 32);
                LDSM_X4(a1[0], a1[1], a1[2], a1[3],
                        aaddr + 16 * GH_STRIDE + ks * 32);
                #pragma unroll
                for (int p = 0; p < 4; ++p) {
                    uint32_t b[4];
                    LDSM_X4(b[0], b[1], b[2], b[3],
                            baddr + p * 16 * GH_STRIDE + ks * 32);
                    MMA16816(acc[0][p * 2 + 0], a0, b[0], b[1]);
                    MMA16816(acc[0][p * 2 + 1], a0, b[2], b[3]);
                    MMA16816(acc[1][p * 2 + 0], a1, b[0], b[1]);
                    MMA16816(acc[1][p * 2 + 1], a1, b[2], b[3]);
                }
            }
        }
    }

    // epilogue: direct stores, bias added
    const int r  = lane >> 2;
    const int c2 = (lane & 3) * 2;
    #pragma unroll
    for (int f = 0; f < 2; ++f) {
        #pragma unroll
        for (int n8 = 0; n8 < 8; ++n8) {
            int n = n0 + wn + n8 * 8 + c2;
            float2 bv = *(const float2*)&bias[n];
            int m = m0 + wm + f * 16 + r;
            float2 r0; r0.x = acc[f][n8][0] + bv.x; r0.y = acc[f][n8][1] + bv.y;
            float2 r1; r1.x = acc[f][n8][2] + bv.x; r1.y = acc[f][n8][3] + bv.y;
            *(float2*)&out[(size_t)m * Hd + n] = r0;
            *(float2*)&out[(size_t)(m + 8) * Hd + n] = r1;
        }
    }
}

// =============================================================================
// Recurrence (R5 exact — measured 1.063ms best): 1 CTA = 1 batch row,
// 512 threads, pair-split j=t>>1/kh=t&1, shfl_xor reduce, one barrier,
// 80 reg / 48 smem weight split, HSTR=132 ping-pong.
// =============================================================================
#define RREG 20
#define RSM  12
#define HSTR 132
#define HBUF (2 * 2 * HSTR)
#define REC_SMEM (HBUF * 4 + RSM * 512 * 16)

__device__ __forceinline__ float fast_tanh(float x) {
    float e = __expf(2.0f * x);
    return 1.0f - 2.0f * __fdividef(1.0f, e + 1.0f);
}

template<bool WRITE_H, bool FINAL>
__global__ void __launch_bounds__(512, 1) recur_kernel(
    const float* __restrict__ pre, const float* __restrict__ Whh,
    float* __restrict__ hout,
    const float* __restrict__ fcw, const float* __restrict__ fcb,
    float* __restrict__ out)
{
    extern __shared__ float smf[];
    float* hbuf = smf;                                   // [2][2*HSTR]
    ulonglong2* Wsm = (ulonglong2*)(smf + HBUF);         // [RSM][512]

    const int t  = threadIdx.x;
    const int b  = blockIdx.x;
    const int j  = t >> 1;
    const int kh = t & 1;

    const ulonglong2* wg =
        (const ulonglong2*)(Whh + (size_t)j * Hd + (kh << 7));
    ulonglong2 wr[RREG];
    #pragma unroll
    for (int c = 0; c < RREG; ++c) wr[c] = wg[c];
    #pragma unroll
    for (int c = 0; c < RSM; ++c) Wsm[c * 512 + t] = wg[RREG + c];

    if (t < HBUF) hbuf[t] = 0.f;

    const float* preb = pre + (size_t)b * Tlen * Hd;
    float p = preb[j];
    const int wslot = j + ((j >> 7) << 2);
    __syncthreads();

    for (int step = 0; step < Tlen; ++step) {
        int sn = (step + 1 < Tlen) ? step + 1 : step;
        float pn = preb[sn * Hd + j];

        const ulonglong2* h2 =
            (const ulonglong2*)(hbuf + (step & 1) * (2 * HSTR) + kh * HSTR);

        u64 a0 = 0ull, a1 = 0ull, a2 = 0ull, a3 = 0ull, a4 = 0ull, a5 = 0ull;

        #pragma unroll
        for (int c = 0; c < RSM; ++c) {
            ulonglong2 hv = h2[RREG + c];
            ulonglong2 wv = Wsm[c * 512 + t];
            fma2(a4, wv.x, hv.x);
            fma2(a5, wv.y, hv.y);
        }
        #pragma unroll
        for (int c = 0; c < RREG; c += 2) {
            ulonglong2 hv = h2[c];
            fma2(a0, wr[c].x, hv.x);
            fma2(a1, wr[c].y, hv.y);
            ulonglong2 hw = h2[c + 1];
            fma2(a2, wr[c + 1].x, hw.x);
            fma2(a3, wr[c + 1].y, hw.y);
        }

        u64 s01 = add2(add2(add2(a0, a1), add2(a2, a3)), add2(a4, a5));
        float2 f = unpk(s01);
        float d = f.x + f.y;
        d += __shfl_xor_sync(0xffffffffu, d, 1);

        float hn = fast_tanh(p + d);

        if (kh == 0) {
            hbuf[((step + 1) & 1) * (2 * HSTR) + wslot] = hn;
            if (WRITE_H)
                hout[((size_t)b * Tlen + step) * Hd + j] = hn;
        }
        __syncthreads();
        p = pn;
    }

    if (FINAL) {
        if (t < 64) {
            int o = t >> 5, lane = t & 31;
            float s = 0.f;
            #pragma unroll
            for (int q = 0; q < 8; ++q) {
                int jj = lane + (q << 5);
                s += hbuf[jj + ((jj >> 7) << 2)] * fcw[o * Hd + jj];
            }
            #pragma unroll
            for (int off = 16; off; off >>= 1)
                s += __shfl_down_sync(0xffffffffu, s, off);
            if (lane == 0) out[b * NOUT + o] = s + fcb[o];
        }
    }
}

extern "C" void kernel_launch(void* const* d_in, const int* in_sizes, int n_in,
                              void* d_out, int out_size) {
    const float* x    = (const float*)d_in[0];
    const float* Wxh0 = (const float*)d_in[1];
    const float* Whh0 = (const float*)d_in[2];
    const float* b0   = (const float*)d_in[3];
    const float* Wxh1 = (const float*)d_in[4];
    const float* Whh1 = (const float*)d_in[5];
    const float* b1   = (const float*)d_in[6];
    const float* fcw  = (const float*)d_in[7];
    const float* fcb  = (const float*)d_in[8];
    float* out = (float*)d_out;

    float *bufA = nullptr, *bufB = nullptr;
    cudaGetSymbolAddress((void**)&bufA, g_bufA);
    cudaGetSymbolAddress((void**)&bufB, g_bufB);

    cudaFuncSetAttribute(gemm_hmma_kernel,
        cudaFuncAttributeMaxDynamicSharedMemorySize, GH_SMEM);
    cudaFuncSetAttribute(recur_kernel<true, false>,
        cudaFuncAttributeMaxDynamicSharedMemorySize, REC_SMEM);
    cudaFuncSetAttribute(recur_kernel<false, true>,
        cudaFuncAttributeMaxDynamicSharedMemorySize, REC_SMEM);

    // Layer 1
    gemm_hmma_kernel<<<2048, 256, GH_SMEM>>>(x, Wxh0, b0, bufA);
    recur_kernel<true, false><<<Bsz, 512, REC_SMEM>>>(
        bufA, Whh0, bufB, nullptr, nullptr, nullptr);

    // Layer 2 + head
    gemm_hmma_kernel<<<2048, 256, GH_SMEM>>>(bufB, Wxh1, b1, bufA);
    recur_kernel<false, true><<<Bsz, 512, REC_SMEM>>>(
        bufA, Whh1, nullptr, fcw, fcb, out);
}

// round 13
// speedup vs baseline: 1.3990x; 1.0777x over previous
#include <cuda_runtime.h>
#include <cuda_bf16.h>
#include <math.h>
#include <cstdint>

#define Bsz  128
#define Tlen 1024
#define Hd   256
#define NOUT 2

typedef unsigned long long u64;

// Scratch buffers (device globals — allocation is forbidden)
__device__ float         g_bufA[Bsz * Tlen * Hd];   // pre-activations (fp32)
__device__ __nv_bfloat16 g_xhi[Bsz * Tlen * Hd];    // x hi
__device__ __nv_bfloat16 g_xlo[Bsz * Tlen * Hd];    // x lo
__device__ __nv_bfloat16 g_h1hi[Bsz * Tlen * Hd];   // h1 hi
__device__ __nv_bfloat16 g_h1lo[Bsz * Tlen * Hd];   // h1 lo
__device__ __nv_bfloat16 g_w0hi[Hd * Hd], g_w0lo[Hd * Hd];
__device__ __nv_bfloat16 g_w1hi[Hd * Hd], g_w1lo[Hd * Hd];

// ---------- packed fp32x2 helpers ----------
__device__ __forceinline__ void fma2(u64& acc, u64 a, u64 b) {
    asm("fma.rn.f32x2 %0, %1, %2, %0;" : "+l"(acc) : "l"(a), "l"(b));
}
__device__ __forceinline__ u64 add2(u64 a, u64 b) {
    u64 r; asm("add.rn.f32x2 %0, %1, %2;" : "=l"(r) : "l"(a), "l"(b)); return r;
}
__device__ __forceinline__ float2 unpk(u64 v) {
    float2 r; asm("mov.b64 {%0, %1}, %2;" : "=f"(r.x), "=f"(r.y) : "l"(v)); return r;
}
__device__ __forceinline__ uint32_t smem_to_u32(const void* p) {
    uint32_t a;
    asm("{ .reg .u64 t; cvta.to.shared.u64 t, %1; cvt.u32.u64 %0, t; }"
        : "=r"(a) : "l"(p));
    return a;
}

// ---------- HMMA helpers ----------
#define LDSM_X4(r0, r1, r2, r3, addr)                                         \
    asm volatile("ldmatrix.sync.aligned.m8n8.x4.shared.b16 {%0,%1,%2,%3}, [%4];" \
                 : "=r"(r0), "=r"(r1), "=r"(r2), "=r"(r3) : "r"(addr))

#define MMA16816(d, a, b0, b1)                                                \
    asm volatile("mma.sync.aligned.m16n8k16.row.col.f32.bf16.bf16.f32 "       \
                 "{%0,%1,%2,%3}, {%4,%5,%6,%7}, {%8,%9}, {%0,%1,%2,%3};"      \
                 : "+f"((d)[0]), "+f"((d)[1]), "+f"((d)[2]), "+f"((d)[3])     \
                 : "r"((a)[0]), "r"((a)[1]), "r"((a)[2]), "r"((a)[3]),        \
                   "r"(b0), "r"(b1))

// =============================================================================
// fp32 -> bf16 hi/lo conversion prepass (vectorized by 4)
// =============================================================================
__global__ void conv_hilo_kernel(const float* __restrict__ src,
                                 __nv_bfloat16* __restrict__ hi,
                                 __nv_bfloat16* __restrict__ lo, int n4)
{
    int i = blockIdx.x * blockDim.x + threadIdx.x;
    if (i >= n4) return;
    float4 v = ((const float4*)src)[i];
    __nv_bfloat162 h01 = __floats2bfloat162_rn(v.x, v.y);
    __nv_bfloat162 h23 = __floats2bfloat162_rn(v.z, v.w);
    float2 f01 = __bfloat1622float2(h01);
    float2 f23 = __bfloat1622float2(h23);
    __nv_bfloat162 l01 = __floats2bfloat162_rn(v.x - f01.x, v.y - f01.y);
    __nv_bfloat162 l23 = __floats2bfloat162_rn(v.z - f23.x, v.w - f23.y);
    uint32_t uh01, uh23, ul01, ul23;
    memcpy(&uh01, &h01, 4); memcpy(&uh23, &h23, 4);
    memcpy(&ul01, &l01, 4); memcpy(&ul23, &l23, 4);
    ((uint2*)hi)[i] = make_uint2(uh01, uh23);
    ((uint2*)lo)[i] = make_uint2(ul01, ul23);
}

// =============================================================================
// HMMA GEMM (copy-staged): out[m][n] = sum_k A[m][k]*W[n][k] + bias[n]
// Inputs pre-converted to bf16 hi/lo. Layout/indexing identical to the R12
// passing kernel; only staging is now pure uint4 copies.
// =============================================================================
#define GH_STRIDE 144                  // bytes per 64-k row (72 bf16)
#define GH_TILE   (128 * GH_STRIDE)    // 18432 B per buffer
#define GH_SMEM   (4 * GH_TILE)        // 73728 B

__global__ void __launch_bounds__(256, 2) gemm_hmma_kernel(
    const __nv_bfloat16* __restrict__ Ahi, const __nv_bfloat16* __restrict__ Alo,
    const __nv_bfloat16* __restrict__ Bhi, const __nv_bfloat16* __restrict__ Blo,
    const float* __restrict__ bias, float* __restrict__ out)
{
    extern __shared__ char smem[];
    char* pAhi = smem;
    char* pAlo = smem + GH_TILE;
    char* pBhi = smem + 2 * GH_TILE;
    char* pBlo = smem + 3 * GH_TILE;
    const uint32_t sAhi = smem_to_u32(pAhi);
    const uint32_t sAlo = sAhi + GH_TILE;
    const uint32_t sBhi = sAhi + 2 * GH_TILE;
    const uint32_t sBlo = sAhi + 3 * GH_TILE;

    const int t    = threadIdx.x;
    const int lane = t & 31;
    const int wid  = t >> 5;
    const int nt   = blockIdx.x & 1;
    const int mt   = blockIdx.x >> 1;
    const int m0   = mt * 128, n0 = nt * 128;
    const int wm   = (wid & 3) * 32;
    const int wn   = (wid >> 2) * 64;

    float acc[2][8][4];
    #pragma unroll
    for (int f = 0; f < 2; ++f)
        #pragma unroll
        for (int n8 = 0; n8 < 8; ++n8)
            #pragma unroll
            for (int e = 0; e < 4; ++e) acc[f][n8][e] = 0.f;

    const __nv_bfloat16* Abh = Ahi + (size_t)m0 * Hd;
    const __nv_bfloat16* Abl = Alo + (size_t)m0 * Hd;
    const __nv_bfloat16* Wbh = Bhi + (size_t)n0 * Hd;
    const __nv_bfloat16* Wbl = Blo + (size_t)n0 * Hd;

    const uint32_t aRowOff = (uint32_t)(lane & 15) * GH_STRIDE +
                             (uint32_t)(lane >> 4) * 16;
    const uint32_t bRowOff = ((uint32_t)((lane >> 4) << 3) + (lane & 7)) * GH_STRIDE +
                             (uint32_t)((lane >> 3) & 1) * 16;

    for (int chunk = 0; chunk < 4; ++chunk) {
        __syncthreads();
        const int kq4 = chunk << 3;            // uint4 index of k-base (64/8*chunk)
        // A tiles: 128 rows x 8 uint4 per buffer (4 iters of 256 threads)
        #pragma unroll
        for (int i = 0; i < 4; ++i) {
            int idx = t + (i << 8);
            int row = idx >> 3, q = idx & 7;
            uint32_t off = (uint32_t)row * GH_STRIDE + (uint32_t)q * 16;
            *(uint4*)(pAhi + off) = ((const uint4*)(Abh + row * Hd))[kq4 + q];
            *(uint4*)(pAlo + off) = ((const uint4*)(Abl + row * Hd))[kq4 + q];
        }
        // B tiles: 128 rows x 8 uint4 per buffer (n0 already applied)
        #pragma unroll
        for (int i = 0; i < 4; ++i) {
            int idx = t + (i << 8);
            int row = idx >> 3, q = idx & 7;
            uint32_t off = (uint32_t)row * GH_STRIDE + (uint32_t)q * 16;
            *(uint4*)(pBhi + off) = ((const uint4*)(Wbh + row * Hd))[kq4 + q];
            *(uint4*)(pBlo + off) = ((const uint4*)(Wbl + row * Hd))[kq4 + q];
        }
        __syncthreads();

        #pragma unroll
        for (int pass = 0; pass < 3; ++pass) {
            const uint32_t ab = (pass == 2) ? sAlo : sAhi;
            const uint32_t bb = (pass == 1) ? sBlo : sBhi;
            const uint32_t aaddr = ab + (uint32_t)wm * GH_STRIDE + aRowOff;
            const uint32_t baddr = bb + (uint32_t)wn * GH_STRIDE + bRowOff;
            #pragma unroll
            for (int ks = 0; ks < 4; ++ks) {
                uint32_t a0[4], a1[4];
                LDSM_X4(a0[0], a0[1], a0[2], a0[3], aaddr + ks * 32);
                LDSM_X4(a1[0], a1[1], a1[2], a1[3],
                        aaddr + 16 * GH_STRIDE + ks * 32);
                #pragma unroll
                for (int p = 0; p < 4; ++p) {
                    uint32_t b[4];
                    LDSM_X4(b[0], b[1], b[2], b[3],
                            baddr + p * 16 * GH_STRIDE + ks * 32);
                    MMA16816(acc[0][p * 2 + 0], a0, b[0], b[1]);
                    MMA16816(acc[0][p * 2 + 1], a0, b[2], b[3]);
                    MMA16816(acc[1][p * 2 + 0], a1, b[0], b[1]);
                    MMA16816(acc[1][p * 2 + 1], a1, b[2], b[3]);
                }
            }
        }
    }

    const int r  = lane >> 2;
    const int c2 = (lane & 3) * 2;
    #pragma unroll
    for (int f = 0; f < 2; ++f) {
        #pragma unroll
        for (int n8 = 0; n8 < 8; ++n8) {
            int n = n0 + wn + n8 * 8 + c2;
            float2 bv = *(const float2*)&bias[n];
            int m = m0 + wm + f * 16 + r;
            float2 r0; r0.x = acc[f][n8][0] + bv.x; r0.y = acc[f][n8][1] + bv.y;
            float2 r1; r1.x = acc[f][n8][2] + bv.x; r1.y = acc[f][n8][3] + bv.y;
            *(float2*)&out[(size_t)m * Hd + n] = r0;
            *(float2*)&out[(size_t)(m + 8) * Hd + n] = r1;
        }
    }
}

// =============================================================================
// Recurrence (R5 structure — 1.063ms): 1 CTA = 1 batch row, 512 threads,
// pair-split j=t>>1/kh=t&1, shfl_xor reduce, one barrier, 80/48 weight split.
// WRITE_H variant emits h as bf16 hi/lo for the next GEMM.
// =============================================================================
#define RREG 20
#define RSM  12
#define HSTR 132
#define HBUF (2 * 2 * HSTR)
#define REC_SMEM (HBUF * 4 + RSM * 512 * 16)

__device__ __forceinline__ float fast_tanh(float x) {
    float e = __expf(2.0f * x);
    return 1.0f - 2.0f * __fdividef(1.0f, e + 1.0f);
}

template<bool WRITE_H, bool FINAL>
__global__ void __launch_bounds__(512, 1) recur_kernel(
    const float* __restrict__ pre, const float* __restrict__ Whh,
    __nv_bfloat16* __restrict__ houthi, __nv_bfloat16* __restrict__ houtlo,
    const float* __restrict__ fcw, const float* __restrict__ fcb,
    float* __restrict__ out)
{
    extern __shared__ float smf[];
    float* hbuf = smf;                                   // [2][2*HSTR]
    ulonglong2* Wsm = (ulonglong2*)(smf + HBUF);         // [RSM][512]

    const int t  = threadIdx.x;
    const int b  = blockIdx.x;
    const int j  = t >> 1;
    const int kh = t & 1;

    const ulonglong2* wg =
        (const ulonglong2*)(Whh + (size_t)j * Hd + (kh << 7));
    ulonglong2 wr[RREG];
    #pragma unroll
    for (int c = 0; c < RREG; ++c) wr[c] = wg[c];
    #pragma unroll
    for (int c = 0; c < RSM; ++c) Wsm[c * 512 + t] = wg[RREG + c];

    if (t < HBUF) hbuf[t] = 0.f;

    const float* preb = pre + (size_t)b * Tlen * Hd;
    float p = preb[j];
    const int wslot = j + ((j >> 7) << 2);
    __syncthreads();

    for (int step = 0; step < Tlen; ++step) {
        int sn = (step + 1 < Tlen) ? step + 1 : step;
        float pn = preb[sn * Hd + j];

        const ulonglong2* h2 =
            (const ulonglong2*)(hbuf + (step & 1) * (2 * HSTR) + kh * HSTR);

        u64 a0 = 0ull, a1 = 0ull, a2 = 0ull, a3 = 0ull, a4 = 0ull, a5 = 0ull;

        #pragma unroll
        for (int c = 0; c < RSM; ++c) {
            ulonglong2 hv = h2[RREG + c];
            ulonglong2 wv = Wsm[c * 512 + t];
            fma2(a4, wv.x, hv.x);
            fma2(a5, wv.y, hv.y);
        }
        #pragma unroll
        for (int c = 0; c < RREG; c += 2) {
            ulonglong2 hv = h2[c];
            fma2(a0, wr[c].x, hv.x);
            fma2(a1, wr[c].y, hv.y);
            ulonglong2 hw = h2[c + 1];
            fma2(a2, wr[c + 1].x, hw.x);
            fma2(a3, wr[c + 1].y, hw.y);
        }

        u64 s01 = add2(add2(add2(a0, a1), add2(a2, a3)), add2(a4, a5));
        float2 f = unpk(s01);
        float d = f.x + f.y;
        d += __shfl_xor_sync(0xffffffffu, d, 1);

        float hn = fast_tanh(p + d);

        if (kh == 0) {
            hbuf[((step + 1) & 1) * (2 * HSTR) + wslot] = hn;
            if (WRITE_H) {
                __nv_bfloat16 hh = __float2bfloat16_rn(hn);
                float rem = hn - __bfloat162float(hh);
                size_t o = ((size_t)b * Tlen + step) * Hd + j;
                houthi[o] = hh;
                houtlo[o] = __float2bfloat16_rn(rem);
            }
        }
        __syncthreads();
        p = pn;
    }

    if (FINAL) {
        if (t < 64) {
            int o = t >> 5, lane = t & 31;
            float s = 0.f;
            #pragma unroll
            for (int q = 0; q < 8; ++q) {
                int jj = lane + (q << 5);
                s += hbuf[jj + ((jj >> 7) << 2)] * fcw[o * Hd + jj];
            }
            #pragma unroll
            for (int off = 16; off; off >>= 1)
                s += __shfl_down_sync(0xffffffffu, s, off);
            if (lane == 0) out[b * NOUT + o] = s + fcb[o];
        }
    }
}

extern "C" void kernel_launch(void* const* d_in, const int* in_sizes, int n_in,
                              void* d_out, int out_size) {
    const float* x    = (const float*)d_in[0];
    const float* Wxh0 = (const float*)d_in[1];
    const float* Whh0 = (const float*)d_in[2];
    const float* b0   = (const float*)d_in[3];
    const float* Wxh1 = (const float*)d_in[4];
    const float* Whh1 = (const float*)d_in[5];
    const float* b1   = (const float*)d_in[6];
    const float* fcw  = (const float*)d_in[7];
    const float* fcb  = (const float*)d_in[8];
    float* out = (float*)d_out;

    float* bufA = nullptr;
    __nv_bfloat16 *xhi, *xlo, *h1hi, *h1lo, *w0hi, *w0lo, *w1hi, *w1lo;
    cudaGetSymbolAddress((void**)&bufA, g_bufA);
    cudaGetSymbolAddress((void**)&xhi, g_xhi);
    cudaGetSymbolAddress((void**)&xlo, g_xlo);
    cudaGetSymbolAddress((void**)&h1hi, g_h1hi);
    cudaGetSymbolAddress((void**)&h1lo, g_h1lo);
    cudaGetSymbolAddress((void**)&w0hi, g_w0hi);
    cudaGetSymbolAddress((void**)&w0lo, g_w0lo);
    cudaGetSymbolAddress((void**)&w1hi, g_w1hi);
    cudaGetSymbolAddress((void**)&w1lo, g_w1lo);

    cudaFuncSetAttribute(gemm_hmma_kernel,
        cudaFuncAttributeMaxDynamicSharedMemorySize, GH_SMEM);
    cudaFuncSetAttribute(recur_kernel<true, false>,
        cudaFuncAttributeMaxDynamicSharedMemorySize, REC_SMEM);
    cudaFuncSetAttribute(recur_kernel<false, true>,
        cudaFuncAttributeMaxDynamicSharedMemorySize, REC_SMEM);

    const int NX4 = (Bsz * Tlen * Hd) / 4;     // 8388608
    const int NW4 = (Hd * Hd) / 4;             // 16384

    // Conversions (x, both input-projection weights)
    conv_hilo_kernel<<<NX4 / 256, 256>>>(x, xhi, xlo, NX4);
    conv_hilo_kernel<<<NW4 / 256, 256>>>(Wxh0, w0hi, w0lo, NW4);
    conv_hilo_kernel<<<NW4 / 256, 256>>>(Wxh1, w1hi, w1lo, NW4);

    // Layer 1
    gemm_hmma_kernel<<<2048, 256, GH_SMEM>>>(xhi, xlo, w0hi, w0lo, b0, bufA);
    recur_kernel<true, false><<<Bsz, 512, REC_SMEM>>>(
        bufA, Whh0, h1hi, h1lo, nullptr, nullptr, nullptr);

    // Layer 2 + head
    gemm_hmma_kernel<<<2048, 256, GH_SMEM>>>(h1hi, h1lo, w1hi, w1lo, b1, bufA);
    recur_kernel<false, true><<<Bsz, 512, REC_SMEM>>>(
        bufA, Whh1, nullptr, nullptr, fcw, fcb, out);
}